// round 7
// baseline (speedup 1.0000x reference)
#include <cuda_runtime.h>
#include <cuda_bf16.h>
#include <cstdint>

// -------- problem constants --------
#define BB      512
#define TT      256
#define D_IN    64
#define D_STATE 64
#define NN      2048
#define D_OUT   10
#define KAUG    128

// -------- decomposition: 16 neuron-groups x 8 batch-groups = 128 CTAs ----
#define NG      16
#define BG      8
#define NT      128     // neurons per CTA (GEMM1 N, GEMM2 K)
#define BT      64      // batch rows per CTA (M)
#define NCTAS   128
#define THREADS 512

// -------- SMEM: interleaved hi/lo bf16 pairs, 32-bit-word addressed -------
// word[row*RSW + 2*p + 0] = hi bf16x2 of pair p, word[... + 1] = lo bf16x2
// RSW = 136 words (= 8 mod 32) -> LDS.64 fragment pattern is conflict-free.
#define RSW     136
#define XA_OFF  0
#define E_OFF   (XA_OFF + BT * RSW)
#define SD_OFF  (E_OFF  + NT * RSW)
#define A2_OFF  (SD_OFF + D_STATE * RSW)
#define SMEM_WORDS (A2_OFF + BT * RSW)
#define SMEM_BYTES (SMEM_WORDS * 4)

// -------- global scratch (static; no allocation) --------
__device__ float g_partials[NG][BB][D_STATE];
__device__ float g_ypart[NG][BB][D_OUT];

// per-bi barriers (padded to separate cache lines); gen monotonic across replays
__device__ unsigned g_cntb[BG * 32];
__device__ volatile unsigned g_genb[BG * 32];

__device__ __forceinline__ void gsync_bi(int bi) {
    __syncthreads();
    if (threadIdx.x == 0) {
        __threadfence();
        unsigned gen = g_genb[bi * 32];            // read BEFORE arriving
        unsigned prev = atomicAdd(&g_cntb[bi * 32], 1);
        if (prev == NG - 1) {
            g_cntb[bi * 32] = 0;
            __threadfence();
            g_genb[bi * 32] = gen + 1;
        } else {
            while (g_genb[bi * 32] == gen) { }
            __threadfence();
        }
    }
    __syncthreads();
}

// -------- warp-level bf16 MMA (sm_80+ baseline PTX; no arch-a gating) -----
__device__ __forceinline__ void mma_bf16(float* c, uint32_t a0, uint32_t a1,
                                         uint32_t a2, uint32_t a3,
                                         uint32_t b0, uint32_t b1) {
    asm volatile(
        "mma.sync.aligned.m16n8k16.row.col.f32.bf16.bf16.f32 "
        "{%0,%1,%2,%3}, {%4,%5,%6,%7}, {%8,%9}, {%0,%1,%2,%3};"
        : "+f"(c[0]), "+f"(c[1]), "+f"(c[2]), "+f"(c[3])
        : "r"(a0), "r"(a1), "r"(a2), "r"(a3), "r"(b0), "r"(b1));
}

// 3-pass split GEMM, 16x32 warp tile, K=128. Each k-step loads A/B hi+lo ONCE
// (LDS.64 on interleaved pairs) and issues passes hh, lh, hl from registers.
__device__ __forceinline__ void gemm3(const uint32_t* __restrict__ A,
                                      const uint32_t* __restrict__ B,
                                      int m0, int n0, int g, int t4,
                                      float acc[4][4]) {
#pragma unroll
    for (int ks = 0; ks < 8; ks++) {
        const int kp0 = ks * 8 + t4;                 // pair index
        const uint32_t* Ar = A + (m0 + g) * RSW;
        uint2 a0 = *(const uint2*)&Ar[2 * kp0];
        uint2 a1 = *(const uint2*)&Ar[8 * RSW + 2 * kp0];
        uint2 a2 = *(const uint2*)&Ar[2 * (kp0 + 4)];
        uint2 a3 = *(const uint2*)&Ar[8 * RSW + 2 * (kp0 + 4)];
#pragma unroll
        for (int ns = 0; ns < 4; ns++) {
            const uint32_t* Bc = B + (n0 + 8 * ns + g) * RSW;
            uint2 b0 = *(const uint2*)&Bc[2 * kp0];
            uint2 b1 = *(const uint2*)&Bc[2 * (kp0 + 4)];
            mma_bf16(acc[ns], a0.x, a1.x, a2.x, a3.x, b0.x, b1.x);  // hi*hi
            mma_bf16(acc[ns], a0.y, a1.y, a2.y, a3.y, b0.x, b1.x);  // lo*hi
            mma_bf16(acc[ns], a0.x, a1.x, a2.x, a3.x, b0.y, b1.y);  // hi*lo
        }
    }
}

// split (x,y) into bf16 hi/lo pairs, store interleaved as one 8B word-pair
__device__ __forceinline__ void split_store(uint32_t* buf, int row, int kp,
                                            float x, float y) {
    __nv_bfloat162 h, l;
    h.x = __float2bfloat16(x);
    h.y = __float2bfloat16(y);
    l.x = __float2bfloat16(x - __bfloat162float(h.x));
    l.y = __float2bfloat16(y - __bfloat162float(h.y));
    uint2 v;
    v.x = *(uint32_t*)&h;
    v.y = *(uint32_t*)&l;
    *(uint2*)&buf[row * RSW + 2 * kp] = v;
}

__global__ void __launch_bounds__(THREADS, 1)
nef_kernel(const float* __restrict__ seq,     // [B][T][D_IN]
           const float* __restrict__ enc,     // [NN][KAUG]
           const float* __restrict__ bias,    // [NN]
           const float* __restrict__ gain,    // [NN]
           const float* __restrict__ sdec,    // [NN][D_STATE]
           const float* __restrict__ dec,     // [NN][D_OUT]
           float* __restrict__ out)           // [B][D_OUT]
{
    extern __shared__ uint32_t smem[];
    uint32_t* XA = smem + XA_OFF;
    uint32_t* E  = smem + E_OFF;
    uint32_t* SD = smem + SD_OFF;
    uint32_t* A2 = smem + A2_OFF;

    const int tid  = threadIdx.x;
    const int wid  = tid >> 5;
    const int lane = tid & 31;
    const int g    = lane >> 2;          // groupID
    const int t4   = lane & 3;           // thread-in-group
    const int ni   = blockIdx.x & (NG - 1);
    const int bi   = blockIdx.x >> 4;
    const int nbase = ni * NT;
    const int bbase = bi * BT;

    // GEMM1 warp tile (16x32): m0a in {0,16,32,48}, n0a in {0,32,64,96}
    const int m0a = 16 * (wid & 3);
    const int n0a = 32 * (wid >> 2);

    // ---- one-time weight staging ----
    for (int i = tid; i < NT * (KAUG / 2); i += THREADS) {
        int n = i >> 6, p = i & 63;
        float2 v = *(const float2*)&enc[(nbase + n) * KAUG + 2 * p];
        split_store(E, n, p, v.x, v.y);
    }
    for (int i = tid; i < D_STATE * (NT / 2); i += THREADS) {
        int d = i >> 6, p = i & 63;
        float x = sdec[(nbase + 2 * p) * D_STATE + d];
        float y = sdec[(nbase + 2 * p + 1) * D_STATE + d];
        split_store(SD, d, p, x, y);
    }
    // per-thread gain/bias for epilogue1 (columns n0a + 8ns + 2t4 (+1))
    float gj[4][2], bj[4][2];
#pragma unroll
    for (int ns = 0; ns < 4; ns++) {
        int n = nbase + n0a + 8 * ns + 2 * t4;
        gj[ns][0] = gain[n];     gj[ns][1] = gain[n + 1];
        bj[ns][0] = bias[n];     bj[ns][1] = bias[n + 1];
    }

    // ---- initial XA = [u(0) | 0] ----
    for (int i = tid; i < BT * (D_IN / 2); i += THREADS) {
        int r = i >> 5, p = i & 31;
        float2 v = *(const float2*)&seq[((size_t)(bbase + r) * TT) * D_IN + 2 * p];
        split_store(XA, r, p, v.x, v.y);
    }
    for (int i = tid; i < BT * (D_STATE / 2); i += THREADS) {
        int r = i >> 5, p = i & 31;
        split_store(XA, r, 32 + p, 0.f, 0.f);
    }
    __syncthreads();

    for (int t = 0; t < TT; t++) {
        // ======== GEMM1: a = XA @ E^T (16 warps, 16x32 tiles) ========
        float acc[4][4];
#pragma unroll
        for (int ns = 0; ns < 4; ns++)
#pragma unroll
            for (int q = 0; q < 4; q++) acc[ns][q] = 0.f;

        gemm3(XA, E, m0a, n0a, g, t4, acc);

        // ======== epilogue 1: act = |gain*v + bias| -> A2 ========
#pragma unroll
        for (int ns = 0; ns < 4; ns++) {
            float v0 = fabsf(fmaf(gj[ns][0], acc[ns][0], bj[ns][0]));
            float v1 = fabsf(fmaf(gj[ns][1], acc[ns][1], bj[ns][1]));
            float v2 = fabsf(fmaf(gj[ns][0], acc[ns][2], bj[ns][0]));
            float v3 = fabsf(fmaf(gj[ns][1], acc[ns][3], bj[ns][1]));
            int r0 = m0a + g;
            int kp = (n0a + 8 * ns) / 2 + t4;
            split_store(A2, r0,     kp, v0, v1);
            split_store(A2, r0 + 8, kp, v2, v3);
        }

        if (t == TT - 1) break;

        __syncthreads();   // A2 visible to GEMM2 warps

        if (wid < 8) {
            // ======== GEMM2: s_part = a @ SD (warps 0-7, 16x32 tiles) ====
            const int m0b = 16 * (wid & 3);
            const int d0b = 32 * (wid >> 2);
            float acc2[4][4];
#pragma unroll
            for (int ns = 0; ns < 4; ns++)
#pragma unroll
                for (int q = 0; q < 4; q++) acc2[ns][q] = 0.f;

            gemm3(A2, SD, m0b, d0b, g, t4, acc2);

#pragma unroll
            for (int ns = 0; ns < 4; ns++) {
                int r0 = m0b + g;
                int d  = d0b + 8 * ns + 2 * t4;
                *(float2*)&g_partials[ni][bbase + r0][d] =
                    make_float2(acc2[ns][0], acc2[ns][1]);
                *(float2*)&g_partials[ni][bbase + r0 + 8][d] =
                    make_float2(acc2[ns][2], acc2[ns][3]);
            }
        } else {
            // ---- concurrent prefetch: u(t+1) -> XA u-part ----
            for (int i = tid - 256; i < BT * (D_IN / 2); i += 256) {
                int r = i >> 5, p = i & 31;
                float2 v = *(const float2*)&seq[((size_t)(bbase + r) * TT + t + 1) * D_IN + 2 * p];
                split_store(XA, r, p, v.x, v.y);
            }
        }

        gsync_bi(bi);   // partials from the 16 ni-sharers of this bi visible

        // ---- fused reduce+fill: s[r][d] = sum_g partials[g][bbase+r][d]
        //      directly into XA s-columns ----
#pragma unroll
        for (int j = 0; j < 2; j++) {
            int item = tid + THREADS * j;        // 0..1023
            int r  = item >> 4;                  // 0..63
            int dq = item & 15;                  // float4 block within d
            float4 s = make_float4(0.f, 0.f, 0.f, 0.f);
#pragma unroll
            for (int gg = 0; gg < NG; gg++) {
                float4 v = *(const float4*)&g_partials[gg][bbase + r][dq * 4];
                s.x += v.x; s.y += v.y; s.z += v.z; s.w += v.w;
            }
            split_store(XA, r, 32 + 2 * dq,     s.x, s.y);
            split_store(XA, r, 32 + 2 * dq + 1, s.z, s.w);
        }
        __syncthreads();
    }

    // ======== final decode: y = a @ dec ========
    __syncthreads();
    for (int idx = tid; idx < BT * D_OUT; idx += THREADS) {
        int b = idx / D_OUT, o = idx - b * D_OUT;
        float s = 0.f;
#pragma unroll 4
        for (int p = 0; p < NT / 2; p++) {
            uint2 w = *(const uint2*)&A2[b * RSW + 2 * p];
            __nv_bfloat162 h = *(__nv_bfloat162*)&w.x;
            __nv_bfloat162 l = *(__nv_bfloat162*)&w.y;
            float a0 = __bfloat162float(h.x) + __bfloat162float(l.x);
            float a1 = __bfloat162float(h.y) + __bfloat162float(l.y);
            s += a0 * dec[(nbase + 2 * p) * D_OUT + o];
            s += a1 * dec[(nbase + 2 * p + 1) * D_OUT + o];
        }
        g_ypart[ni][bbase + b][o] = s;
    }
    gsync_bi(bi);

    if (ni == 0) {
        for (int idx = tid; idx < BT * D_OUT; idx += THREADS) {
            int b = idx / D_OUT, o = idx - b * D_OUT;
            float s = 0.f;
#pragma unroll
            for (int gg = 0; gg < NG; gg++)
                s += g_ypart[gg][bbase + b][o];
            out[(bbase + b) * D_OUT + o] = s;
        }
    }
}

extern "C" void kernel_launch(void* const* d_in, const int* in_sizes, int n_in,
                              void* d_out, int out_size) {
    (void)in_sizes; (void)n_in; (void)out_size;
    cudaFuncSetAttribute(nef_kernel, cudaFuncAttributeMaxDynamicSharedMemorySize,
                         SMEM_BYTES);
    nef_kernel<<<NCTAS, THREADS, SMEM_BYTES>>>(
        (const float*)d_in[0],   // seq
        (const float*)d_in[1],   // encoders
        (const float*)d_in[2],   // bias
        (const float*)d_in[3],   // gain
        (const float*)d_in[4],   // state_decoders
        (const float*)d_in[5],   // decoders
        (float*)d_out);
}